// round 1
// baseline (speedup 1.0000x reference)
#include <cuda_runtime.h>

#define NU 8192
#define NI 4096
#define DE 64
#define NNZ_MAX (1<<19)
#define EPSF 1e-7f
#define OU (NU*192)

// ---------------- scratch (device globals; no allocations) ----------------
__device__ int g_nnz;
__device__ int g_ucnt[NU];
__device__ int g_icnt[NI];
__device__ int g_uptr[NU+1];
__device__ int g_iptr[NI+1];
__device__ int g_ucur[NU];
__device__ int g_icur[NI];
__device__ int g_ucols[NNZ_MAX];   // CSR of H   (rows = users, cols = items)
__device__ int g_icols[NNZ_MAX];   // CSR of H^T (rows = items, cols = users)
__device__ unsigned int g_coo[NNZ_MAX];

__device__ float g_g1[NI], g_hci[NU];
__device__ float g_dvu[NU], g_de1u[NI], g_de2u[NI];
__device__ float g_dvi[NI], g_de1i[NU], g_de2i[NU];

__device__ float g_Xu[NU*DE], g_Xi[NI*DE];
__device__ float g_Y1u[NI*DE], g_Y1i[NU*DE];
__device__ float g_An[NU*DE], g_Am[NI*DE];   // user-side ping-pong
__device__ float g_Bn[NI*DE], g_Bm[NU*DE];   // item-side ping-pong

// ---------------- setup kernels ----------------
__global__ void k_zero() {
    int i = blockIdx.x*blockDim.x + threadIdx.x;
    if (i < NU) g_ucnt[i] = 0;
    if (i < NI) g_icnt[i] = 0;
    if (i == 0) g_nnz = 0;
}

// one block per user row: scan dense H, emit COO + row/col counts (single 128MB pass)
__global__ void k_scan(const float4* __restrict__ H) {
    __shared__ int s_cnt;
    int u = blockIdx.x;
    if (threadIdx.x == 0) s_cnt = 0;
    __syncthreads();
    const float4* row = H + (size_t)u * (NI/4);
    int cols[16]; int n = 0;
    #pragma unroll
    for (int k = 0; k < 4; k++) {
        int j = threadIdx.x + k*256;
        float4 v = row[j];
        int c0 = j*4;
        if (v.x != 0.f) cols[n++] = c0;
        if (v.y != 0.f) cols[n++] = c0+1;
        if (v.z != 0.f) cols[n++] = c0+2;
        if (v.w != 0.f) cols[n++] = c0+3;
    }
    if (n) {
        atomicAdd(&s_cnt, n);
        int base = atomicAdd(&g_nnz, n);
        for (int e = 0; e < n; e++) {
            int p = base + e;
            if (p < NNZ_MAX) g_coo[p] = ((unsigned)u << 12) | (unsigned)cols[e];
            atomicAdd(&g_icnt[cols[e]], 1);
        }
    }
    __syncthreads();
    if (threadIdx.x == 0) g_ucnt[u] = s_cnt;
}

// block 0: exclusive scan user counts; block 1: item counts
__global__ void k_scanptr() {
    __shared__ int sh[1024];
    int tid = threadIdx.x;
    int n        = (blockIdx.x == 0) ? NU : NI;
    const int* cnt = (blockIdx.x == 0) ? g_ucnt : g_icnt;
    int* ptr     = (blockIdx.x == 0) ? g_uptr : g_iptr;
    int* cur     = (blockIdx.x == 0) ? g_ucur : g_icur;
    int chunk = n >> 10;           // 8 or 4
    int base = tid * chunk;
    int loc[8]; int s = 0;
    #pragma unroll
    for (int k = 0; k < 8; k++) if (k < chunk) { loc[k] = s; s += cnt[base+k]; }
    sh[tid] = s; __syncthreads();
    for (int off = 1; off < 1024; off <<= 1) {
        int add = (tid >= off) ? sh[tid-off] : 0;
        __syncthreads();
        sh[tid] += add;
        __syncthreads();
    }
    int mb = sh[tid] - s;
    #pragma unroll
    for (int k = 0; k < 8; k++) if (k < chunk) { int v = mb + loc[k]; ptr[base+k] = v; cur[base+k] = v; }
    if (tid == 1023) ptr[n] = sh[1023];
}

__global__ void k_scatter() {
    int idx = blockIdx.x*blockDim.x + threadIdx.x;
    int n = g_nnz;
    if (idx >= n) return;
    unsigned e = g_coo[idx];
    int u = e >> 12, i = e & 0xFFF;
    int p = atomicAdd(&g_ucur[u], 1); g_ucols[p] = i;
    int q = atomicAdd(&g_icur[i], 1); g_icols[q] = u;
}

// ---------------- norm vectors (warp per row) ----------------
__global__ void k_norm1() {
    int gw = (blockIdx.x*blockDim.x + threadIdx.x) >> 5;
    int lane = threadIdx.x & 31;
    float s = 0.f;
    if (gw < NI) {                       // g1 = H^T * rowsum(H)
        int i = gw, b = g_iptr[i], e = g_iptr[i+1];
        for (int t = b+lane; t < e; t += 32) s += (float)g_ucnt[g_icols[t]];
        for (int o = 16; o; o >>= 1) s += __shfl_down_sync(~0u, s, o);
        if (!lane) g_g1[i] = s;
    } else if (gw < NI+NU) {             // hci = H * colsum(H)
        int u = gw - NI, b = g_uptr[u], e = g_uptr[u+1];
        for (int t = b+lane; t < e; t += 32) s += (float)g_icnt[g_ucols[t]];
        for (int o = 16; o; o >>= 1) s += __shfl_down_sync(~0u, s, o);
        if (!lane) g_hci[u] = s;
    }
}

__global__ void k_norm2() {
    int gw = (blockIdx.x*blockDim.x + threadIdx.x) >> 5;
    int lane = threadIdx.x & 31;
    float s = 0.f;
    if (gw < NU) {                       // hg1 = H * g1 ; user-side + item-side scalars
        int u = gw, b = g_uptr[u], e = g_uptr[u+1];
        for (int t = b+lane; t < e; t += 32) s += g_g1[g_ucols[t]];
        for (int o = 16; o; o >>= 1) s += __shfl_down_sync(~0u, s, o);
        if (!lane) {
            float ru = (float)g_ucnt[u];
            g_dvu[u]  = rsqrtf(ru + s + EPSF);
            g_de1i[u] = 1.0f / (ru + EPSF);
            g_de2i[u] = 1.0f / (s + EPSF);
        }
    } else if (gw < NU+NI) {             // cg = H^T * hci
        int i = gw - NU, b = g_iptr[i], e = g_iptr[i+1];
        for (int t = b+lane; t < e; t += 32) s += g_hci[g_icols[t]];
        for (int o = 16; o; o >>= 1) s += __shfl_down_sync(~0u, s, o);
        if (!lane) {
            float ci = (float)g_icnt[i];
            g_dvi[i]  = rsqrtf(ci + s + EPSF);
            g_de1u[i] = 1.0f / (ci + EPSF);
            g_de2u[i] = 1.0f / (s + EPSF);
        }
    }
}

// copy embeddings into working buffers + level-0 slots of the output
__global__ void k_init(const float* __restrict__ ue, const float* __restrict__ ie,
                       float* __restrict__ out) {
    int idx = blockIdx.x*blockDim.x + threadIdx.x;
    if (idx < NU*DE) {
        float v = ue[idx]; g_Xu[idx] = v;
        int r = idx >> 6, c = idx & 63;
        out[r*192 + c] = v;
    }
    int j = idx - NU*DE;
    if (j >= 0 && j < NI*DE) {
        float v = ie[j]; g_Xi[j] = v;
        int r = j >> 6, c = j & 63;
        out[OU + r*192 + c] = v;
    }
}

// ---------------- SpMM (warp per output row, 64-wide as float2) ----------------
struct Job {
    const int* ptr; const int* cols;
    const float* X; float* out;
    const float* cs;            // optional col scale (indexed by gathered col)
    const float* rs;            // optional init row scale
    const float* init;          // optional init source
    int nrows;
};

template<bool CS, bool INIT>
__global__ void k_spmm(Job a, Job b) {
    int gw = (blockIdx.x*blockDim.x + threadIdx.x) >> 5;
    int lane = threadIdx.x & 31;
    const Job& j = (gw < a.nrows) ? a : b;
    int row = (gw < a.nrows) ? gw : gw - a.nrows;
    if (row >= j.nrows) return;
    int s = j.ptr[row], e = j.ptr[row+1];
    float2 acc = make_float2(0.f, 0.f);
    if (INIT) {
        float r0 = j.rs[row];
        float2 v = ((const float2*)j.init)[row*32 + lane];
        acc.x = r0*v.x; acc.y = r0*v.y;
    }
    const float2* X2 = (const float2*)j.X;
    #pragma unroll 4
    for (int t = s; t < e; t++) {
        int c = __ldg(&j.cols[t]);
        float sc = CS ? __ldg(&j.cs[c]) : 1.0f;
        float2 v = __ldg(&X2[c*32 + lane]);
        acc.x += sc*v.x; acc.y += sc*v.y;
    }
    ((float2*)j.out)[row*32 + lane] = acc;
}

// ---------------- final stage: Z = Hm*S ; M = dv*Z + X ; next = M@w + b ----------------
struct FJob {
    const int* ptr; const int* cols;
    const float* S; float* Xbuf; const float* dv;
    const float* w; const float* b;
    float* outp;                 // d_out + side offset + 64*(layer+1)
    int nrows;
};

__global__ void k_final(FJob a, FJob b) {
    int gw = (blockIdx.x*blockDim.x + threadIdx.x) >> 5;
    int lane = threadIdx.x & 31;
    const FJob& j = (gw < a.nrows) ? a : b;
    int row = (gw < a.nrows) ? gw : gw - a.nrows;
    if (row >= j.nrows) return;
    int s = j.ptr[row], e = j.ptr[row+1];
    float2 acc = make_float2(0.f, 0.f);
    const float2* S2 = (const float2*)j.S;
    #pragma unroll 4
    for (int t = s; t < e; t++) {
        int c = __ldg(&j.cols[t]);
        float2 v = __ldg(&S2[c*32 + lane]);
        acc.x += v.x; acc.y += v.y;
    }
    float dvr = j.dv[row];
    float2 x0 = ((const float2*)j.Xbuf)[row*32 + lane];
    float2 m = make_float2(dvr*acc.x + x0.x, dvr*acc.y + x0.y);
    // fused 64x64 GEMM via warp shuffles: out[c] = sum_k m[k]*w[k,c] + b[c]
    const float2* W2 = (const float2*)j.w;
    float2 o = ((const float2*)j.b)[lane];
    #pragma unroll
    for (int k = 0; k < 64; k++) {
        float mk = __shfl_sync(~0u, (k & 1) ? m.y : m.x, k >> 1);
        float2 wk = __ldg(&W2[k*32 + lane]);
        o.x += mk*wk.x; o.y += mk*wk.y;
    }
    ((float2*)j.Xbuf)[row*32 + lane] = o;
    float* op = j.outp + (size_t)row * 192;
    ((float2*)op)[lane] = o;
}

// ---------------- host launch ----------------
#define GETSYM(var, type, symname) type var; { void* _t = nullptr; cudaGetSymbolAddress(&_t, symname); var = (type)_t; }

extern "C" void kernel_launch(void* const* d_in, const int* in_sizes, int n_in,
                              void* d_out, int out_size) {
    const float* H  = (const float*)d_in[0];
    const float* ue = (const float*)d_in[1];
    const float* ie = (const float*)d_in[2];
    const float* wv[2] = { (const float*)d_in[3], (const float*)d_in[5] };
    const float* bv[2] = { (const float*)d_in[4], (const float*)d_in[6] };
    float* out = (float*)d_out;

    GETSYM(p_uptr,  const int*, g_uptr);   GETSYM(p_iptr,  const int*, g_iptr);
    GETSYM(p_ucols, const int*, g_ucols);  GETSYM(p_icols, const int*, g_icols);
    GETSYM(p_dvu,   const float*, g_dvu);  GETSYM(p_dvi,   const float*, g_dvi);
    GETSYM(p_de1u,  const float*, g_de1u); GETSYM(p_de2u,  const float*, g_de2u);
    GETSYM(p_de1i,  const float*, g_de1i); GETSYM(p_de2i,  const float*, g_de2i);
    GETSYM(p_Xu,  float*, g_Xu);   GETSYM(p_Xi,  float*, g_Xi);
    GETSYM(p_Y1u, float*, g_Y1u);  GETSYM(p_Y1i, float*, g_Y1i);
    GETSYM(p_An,  float*, g_An);   GETSYM(p_Am,  float*, g_Am);
    GETSYM(p_Bn,  float*, g_Bn);   GETSYM(p_Bm,  float*, g_Bm);

    const int WBLK = 1536;   // (NU+NI) warps / 8 warps-per-block

    k_zero<<<32, 256>>>();
    k_scan<<<NU, 256>>>((const float4*)H);
    k_scanptr<<<2, 1024>>>();
    k_scatter<<<NNZ_MAX/256, 256>>>();
    k_norm1<<<WBLK, 256>>>();
    k_norm2<<<WBLK, 256>>>();
    k_init<<<((NU+NI)*DE)/256, 256>>>(ue, ie, out);

    for (int l = 0; l < 2; l++) {
        Job ja, jb;
        // S1: Y1 = Hm^T (dv ⊙ X)
        ja = { p_iptr, p_icols, p_Xu, p_Y1u, p_dvu, nullptr, nullptr, NI };
        jb = { p_uptr, p_ucols, p_Xi, p_Y1i, p_dvi, nullptr, nullptr, NU };
        k_spmm<true, false><<<WBLK, 256>>>(ja, jb);
        // S2: P = Hm Y1
        ja = { p_uptr, p_ucols, p_Y1u, p_An, nullptr, nullptr, nullptr, NU };
        jb = { p_iptr, p_icols, p_Y1i, p_Bn, nullptr, nullptr, nullptr, NI };
        k_spmm<false, false><<<WBLK, 256>>>(ja, jb);
        // S3: Y2 = Hm^T P
        ja = { p_iptr, p_icols, p_An, p_Am, nullptr, nullptr, nullptr, NI };
        jb = { p_uptr, p_ucols, p_Bn, p_Bm, nullptr, nullptr, nullptr, NU };
        k_spmm<false, false><<<WBLK, 256>>>(ja, jb);
        // S4: Q = Hm (de2^2 ⊙ Y2)
        ja = { p_uptr, p_ucols, p_Am, p_An, p_de2u, nullptr, nullptr, NU };
        jb = { p_iptr, p_icols, p_Bm, p_Bn, p_de2i, nullptr, nullptr, NI };
        k_spmm<true, false><<<WBLK, 256>>>(ja, jb);
        // S5: S = de1^2 ⊙ Y1 + Hm^T Q
        ja = { p_iptr, p_icols, p_An, p_Am, nullptr, p_de1u, p_Y1u, NI };
        jb = { p_uptr, p_ucols, p_Bn, p_Bm, nullptr, p_de1i, p_Y1i, NU };
        k_spmm<false, true><<<WBLK, 256>>>(ja, jb);
        // S6: M = dv ⊙ (Hm S) + X ; X_next = M @ w + b  (also writes output slice)
        FJob fa = { p_uptr, p_ucols, p_Am, p_Xu, p_dvu, wv[l], bv[l], out + 64*(l+1),      NU };
        FJob fb = { p_iptr, p_icols, p_Bm, p_Xi, p_dvi, wv[l], bv[l], out + OU + 64*(l+1), NI };
        k_final<<<WBLK, 256>>>(fa, fb);
    }
}

// round 2
// speedup vs baseline: 1.0144x; 1.0144x over previous
#include <cuda_runtime.h>

#define NU 8192
#define NI 4096
#define DE 64
#define US 64          // ELL stride, user rows (deg ~Poisson(20.5))
#define IS 96          // ELL stride, item rows (deg ~Poisson(41))
#define EPSF 1e-7f
#define OU (NU*192)
#define NBLK 592       // 148 SMs * 4 CTAs — co-resident by __launch_bounds__(256,4)
#define NTHR 256

// ---------------- device scratch (no allocations) ----------------
__device__ int g_ucnt[NU];
__device__ int g_icnt[NI];
__device__ int g_ucols[NU*US];     // ELL rows of H   (user -> items)
__device__ int g_icols[NI*IS];     // ELL rows of H^T (item -> users)

__device__ float g_g1[NI], g_hci[NU];
__device__ float g_dvu[NU], g_de1u[NI], g_de2u[NI];
__device__ float g_dvi[NI], g_de1i[NU], g_de2i[NU];

__device__ float g_Xu[NU*DE], g_Xi[NI*DE];
__device__ float g_Y1u[NI*DE], g_Y1i[NU*DE];
__device__ float g_An[NU*DE], g_Am[NI*DE];
__device__ float g_Bn[NI*DE], g_Bm[NU*DE];

__device__ unsigned g_bar_count = 0;
__device__ volatile unsigned g_bar_gen = 0;

// software grid barrier; safe because all NBLK blocks are co-resident
__device__ __forceinline__ void gsync() {
    __syncthreads();
    if (threadIdx.x == 0) {
        __threadfence();                       // release (also CCTL.IVALL -> L1 flush)
        unsigned gen = g_bar_gen;
        if (atomicAdd(&g_bar_count, 1u) == gridDim.x - 1) {
            g_bar_count = 0;
            __threadfence();
            g_bar_gen = gen + 1;
        } else {
            while (g_bar_gen == gen) __nanosleep(32);
        }
        __threadfence();                       // acquire side: flush stale L1 lines
    }
    __syncthreads();
}

// ---------------- SpMM over two independent halves (warp per row) ----------------
struct Half {
    const int* cols; int stride; const int* cnt;
    const float* X; float* out;
    const float* cs; const float* rs; const float* init;
    int n;
};

template<bool CS, bool INIT>
__device__ __forceinline__ void spmm_pair(const Half& A, const Half& B,
                                          int gw, int nwarp, int lane) {
    int ntot = A.n + B.n;
    for (int r = gw; r < ntot; r += nwarp) {
        const Half& J = (r < A.n) ? A : B;
        int row = (r < A.n) ? r : r - A.n;
        int n = min(__ldcg(&J.cnt[row]), J.stride);
        const int* cp = J.cols + row * J.stride;
        float2 acc = make_float2(0.f, 0.f);
        if (INIT) {
            float r0 = __ldcg(&J.rs[row]);
            float2 v = __ldcg((const float2*)J.init + row*32 + lane);
            acc.x = r0 * v.x; acc.y = r0 * v.y;
        }
        const float2* X2 = (const float2*)J.X;
        #pragma unroll 4
        for (int t = 0; t < n; t++) {
            int c = __ldcg(&cp[t]);
            float sc = CS ? __ldcg(&J.cs[c]) : 1.0f;
            float2 v = __ldcg(&X2[c*32 + lane]);
            acc.x += sc * v.x; acc.y += sc * v.y;
        }
        ((float2*)J.out)[row*32 + lane] = acc;
    }
}

// ---------------- final: Z=Hm*S ; M=dv*Z+X ; X'=M@w+b ; write out slice ----------------
struct FHalf {
    const int* cols; int stride; const int* cnt;
    const float* S; float* Xbuf; const float* dv;
    float* outp; int n;
};

__device__ __forceinline__ void final_pair(const FHalf& A, const FHalf& B,
                                           const float* w, const float* b,
                                           int gw, int nwarp, int lane) {
    int ntot = A.n + B.n;
    for (int r = gw; r < ntot; r += nwarp) {
        const FHalf& J = (r < A.n) ? A : B;
        int row = (r < A.n) ? r : r - A.n;
        int n = min(__ldcg(&J.cnt[row]), J.stride);
        const int* cp = J.cols + row * J.stride;
        float2 acc = make_float2(0.f, 0.f);
        const float2* S2 = (const float2*)J.S;
        #pragma unroll 4
        for (int t = 0; t < n; t++) {
            int c = __ldcg(&cp[t]);
            float2 v = __ldcg(&S2[c*32 + lane]);
            acc.x += v.x; acc.y += v.y;
        }
        float dvr = __ldcg(&J.dv[row]);
        float2 x0 = __ldcg((const float2*)J.Xbuf + row*32 + lane);
        float2 m = make_float2(dvr*acc.x + x0.x, dvr*acc.y + x0.y);
        const float2* W2 = (const float2*)w;
        float2 o = __ldg((const float2*)b + lane);
        #pragma unroll
        for (int k = 0; k < 64; k++) {
            float mk = __shfl_sync(~0u, (k & 1) ? m.y : m.x, k >> 1);
            float2 wk = __ldg(&W2[k*32 + lane]);
            o.x += mk*wk.x; o.y += mk*wk.y;
        }
        ((float2*)J.Xbuf)[row*32 + lane] = o;
        ((float2*)(J.outp + (size_t)row * 192))[lane] = o;
    }
}

// ---------------- the single persistent kernel ----------------
__global__ void __launch_bounds__(NTHR, 4) k_all(
    const float4* __restrict__ H,
    const float* __restrict__ ue, const float* __restrict__ ie,
    const float* __restrict__ w0, const float* __restrict__ b0,
    const float* __restrict__ w1, const float* __restrict__ b1,
    float* __restrict__ out)
{
    const int tid  = blockIdx.x * NTHR + threadIdx.x;
    const int nthr = gridDim.x * NTHR;
    const int gw   = tid >> 5, nwarp = nthr >> 5, lane = threadIdx.x & 31;

    // ---- stage 0: zero counters + copy embeddings + level-0 output slices ----
    for (int i = tid; i < NU; i += nthr) g_ucnt[i] = 0;
    for (int i = tid; i < NI; i += nthr) g_icnt[i] = 0;
    for (int i = tid; i < NU*DE; i += nthr) {
        float v = ue[i]; g_Xu[i] = v;
        out[(i >> 6)*192 + (i & 63)] = v;
    }
    for (int i = tid; i < NI*DE; i += nthr) {
        float v = ie[i]; g_Xi[i] = v;
        out[OU + (i >> 6)*192 + (i & 63)] = v;
    }
    gsync();

    // ---- stage 1: scan dense H once, build ELL CSR + CSC directly ----
    for (int idx = tid; idx < NU*(NI/4); idx += nthr) {
        float4 v = __ldcs(&H[idx]);
        if (v.x != 0.f || v.y != 0.f || v.z != 0.f || v.w != 0.f) {
            int u  = idx >> 10;
            int c0 = (idx & 1023) << 2;
            float f[4] = {v.x, v.y, v.z, v.w};
            #pragma unroll
            for (int k = 0; k < 4; k++) {
                if (f[k] != 0.f) {
                    int c = c0 + k;
                    int p = atomicAdd(&g_ucnt[u], 1); if (p < US) g_ucols[u*US + p] = c;
                    int q = atomicAdd(&g_icnt[c], 1); if (q < IS) g_icols[c*IS + q] = u;
                }
            }
        }
    }
    gsync();

    // ---- stage 2: norm pass 1 — g1 = H^T * rowsum(H) ; hci = H * colsum(H) ----
    for (int r = gw; r < NI + NU; r += nwarp) {
        float s = 0.f;
        if (r < NI) {
            int i = r, n = min(__ldcg(&g_icnt[i]), IS);
            const int* cp = g_icols + i*IS;
            for (int t = lane; t < n; t += 32) s += (float)__ldcg(&g_ucnt[__ldcg(&cp[t])]);
            for (int o = 16; o; o >>= 1) s += __shfl_down_sync(~0u, s, o);
            if (!lane) g_g1[i] = s;
        } else {
            int u = r - NI, n = min(__ldcg(&g_ucnt[u]), US);
            const int* cp = g_ucols + u*US;
            for (int t = lane; t < n; t += 32) s += (float)__ldcg(&g_icnt[__ldcg(&cp[t])]);
            for (int o = 16; o; o >>= 1) s += __shfl_down_sync(~0u, s, o);
            if (!lane) g_hci[u] = s;
        }
    }
    gsync();

    // ---- stage 3: norm pass 2 — dv / de1 / de2 for both sides ----
    for (int r = gw; r < NU + NI; r += nwarp) {
        float s = 0.f;
        if (r < NU) {
            int u = r, n = min(__ldcg(&g_ucnt[u]), US);
            const int* cp = g_ucols + u*US;
            for (int t = lane; t < n; t += 32) s += __ldcg(&g_g1[__ldcg(&cp[t])]);
            for (int o = 16; o; o >>= 1) s += __shfl_down_sync(~0u, s, o);
            if (!lane) {
                float ru = (float)__ldcg(&g_ucnt[u]);
                g_dvu[u]  = rsqrtf(ru + s + EPSF);
                g_de1i[u] = 1.0f / (ru + EPSF);
                g_de2i[u] = 1.0f / (s + EPSF);
            }
        } else {
            int i = r - NU, n = min(__ldcg(&g_icnt[i]), IS);
            const int* cp = g_icols + i*IS;
            for (int t = lane; t < n; t += 32) s += __ldcg(&g_hci[__ldcg(&cp[t])]);
            for (int o = 16; o; o >>= 1) s += __shfl_down_sync(~0u, s, o);
            if (!lane) {
                float ci = (float)__ldcg(&g_icnt[i]);
                g_dvi[i]  = rsqrtf(ci + s + EPSF);
                g_de1u[i] = 1.0f / (ci + EPSF);
                g_de2u[i] = 1.0f / (s + EPSF);
            }
        }
    }
    gsync();

    // ---- two layers ----
    const float* wv[2] = { w0, w1 };
    const float* bv[2] = { b0, b1 };
    for (int l = 0; l < 2; l++) {
        Half a, b2;
        // S1: Y1 = Hm^T (dv ⊙ X)
        a  = { g_icols, IS, g_icnt, g_Xu, g_Y1u, g_dvu, nullptr, nullptr, NI };
        b2 = { g_ucols, US, g_ucnt, g_Xi, g_Y1i, g_dvi, nullptr, nullptr, NU };
        spmm_pair<true, false>(a, b2, gw, nwarp, lane);
        gsync();
        // S2: P = Hm Y1
        a  = { g_ucols, US, g_ucnt, g_Y1u, g_An, nullptr, nullptr, nullptr, NU };
        b2 = { g_icols, IS, g_icnt, g_Y1i, g_Bn, nullptr, nullptr, nullptr, NI };
        spmm_pair<false, false>(a, b2, gw, nwarp, lane);
        gsync();
        // S3: Y2 = Hm^T P
        a  = { g_icols, IS, g_icnt, g_An, g_Am, nullptr, nullptr, nullptr, NI };
        b2 = { g_ucols, US, g_ucnt, g_Bn, g_Bm, nullptr, nullptr, nullptr, NU };
        spmm_pair<false, false>(a, b2, gw, nwarp, lane);
        gsync();
        // S4: Q = Hm (de2^2 ⊙ Y2)
        a  = { g_ucols, US, g_ucnt, g_Am, g_An, g_de2u, nullptr, nullptr, NU };
        b2 = { g_icols, IS, g_icnt, g_Bm, g_Bn, g_de2i, nullptr, nullptr, NI };
        spmm_pair<true, false>(a, b2, gw, nwarp, lane);
        gsync();
        // S5: S = de1^2 ⊙ Y1 + Hm^T Q
        a  = { g_icols, IS, g_icnt, g_An, g_Am, nullptr, g_de1u, g_Y1u, NI };
        b2 = { g_ucols, US, g_ucnt, g_Bn, g_Bm, nullptr, g_de1i, g_Y1i, NU };
        spmm_pair<false, true>(a, b2, gw, nwarp, lane);
        gsync();
        // S6: M = dv ⊙ (Hm S) + X ; X' = M@w + b ; write output slice l+1
        FHalf fa = { g_ucols, US, g_ucnt, g_Am, g_Xu, g_dvu, out + 64*(l+1),      NU };
        FHalf fb = { g_icols, IS, g_icnt, g_Bm, g_Xi, g_dvi, out + OU + 64*(l+1), NI };
        final_pair(fa, fb, wv[l], bv[l], gw, nwarp, lane);
        if (l == 0) gsync();
    }
}

// ---------------- host launch: ONE kernel, graph-capturable ----------------
extern "C" void kernel_launch(void* const* d_in, const int* in_sizes, int n_in,
                              void* d_out, int out_size) {
    const float4* H  = (const float4*)d_in[0];
    const float*  ue = (const float*)d_in[1];
    const float*  ie = (const float*)d_in[2];
    const float*  w0 = (const float*)d_in[3];
    const float*  b0 = (const float*)d_in[4];
    const float*  w1 = (const float*)d_in[5];
    const float*  b1 = (const float*)d_in[6];
    float* out = (float*)d_out;

    k_all<<<NBLK, NTHR>>>(H, ue, ie, w0, b0, w1, b1, out);
}

// round 3
// speedup vs baseline: 1.2794x; 1.2612x over previous
#include <cuda_runtime.h>

#define NU 8192
#define NI 4096
#define DE 64
#define US 64          // ELL stride, user rows (deg ~Poisson(20.5))
#define IS 96          // ELL stride, item rows (deg ~Poisson(41))
#define EPSF 1e-7f
#define OU (NU*192)
#define NBLK 592       // 148 SMs * 4 CTAs — co-resident via __launch_bounds__(256,4)
#define NTHR 256

// ---------------- device scratch (no allocations) ----------------
__device__ int g_ucnt[NU];
__device__ int g_icnt[NI];
__device__ int g_ucols[NU*US];     // ELL rows of H   (user -> items)
__device__ int g_icols[NI*IS];     // ELL rows of H^T (item -> users)

__device__ float g_g1[NI], g_hci[NU];
__device__ float g_dvu[NU], g_de1u[NI], g_de2u[NI];
__device__ float g_dvi[NI], g_de1i[NU], g_de2i[NU];

__device__ float g_Xu[NU*DE],  g_Xi[NI*DE];
__device__ float g_Xsu[NU*DE], g_Xsi[NI*DE];   // dv ⊙ X (prescaled for S1)
__device__ float g_Y1u[NI*DE], g_Y1i[NU*DE];
__device__ float g_An[NU*DE],  g_Am[NI*DE];
__device__ float g_Bn[NI*DE],  g_Bm[NU*DE];

__device__ unsigned g_bar_count = 0;
__device__ volatile unsigned g_bar_gen = 0;

// software grid barrier; all NBLK blocks co-resident. __threadfence (gpu scope)
// emits CCTL.IVALL -> L1 flushed on both release and acquire sides, so plain
// L1-cached loads of mutable globals are safe between stages.
__device__ __forceinline__ void gsync() {
    __syncthreads();
    if (threadIdx.x == 0) {
        __threadfence();
        unsigned gen = g_bar_gen;
        if (atomicAdd(&g_bar_count, 1u) == gridDim.x - 1) {
            g_bar_count = 0;
            __threadfence();
            g_bar_gen = gen + 1;
        } else {
            while (g_bar_gen == gen) __nanosleep(32);
        }
        __threadfence();
    }
    __syncthreads();
}

// ---------------- SpMM over two independent halves (warp per row) ----------------
// inner loop is pure gather+add: indices prefetched coalesced, fed via shfl
struct Half {
    const int* cols; int stride; const int* cnt;
    const float* X; float* out;
    const float* rs;            // row scale: INIT -> init coeff, RSOUT -> store scale
    const float* init;
    int n;
};

template<bool RSOUT, bool INIT>
__device__ __forceinline__ void spmm_pair(const Half& A, const Half& B,
                                          int gw, int nwarp, int lane) {
    int ntot = A.n + B.n;
    for (int r = gw; r < ntot; r += nwarp) {
        const Half& J = (r < A.n) ? A : B;
        int row = (r < A.n) ? r : r - A.n;
        int n = min(J.cnt[row], J.stride);
        const int* cp = J.cols + row * J.stride;
        int i0 = 0, i1 = 0, i2 = 0;                 // coalesced index burst
        if (lane      < n) i0 = cp[lane];
        if (lane + 32 < n) i1 = cp[lane + 32];
        if (lane + 64 < n) i2 = cp[lane + 64];
        float2 acc = make_float2(0.f, 0.f);
        if (INIT) {
            float r0 = J.rs[row];
            float2 v = ((const float2*)J.init)[row*32 + lane];
            acc.x = r0 * v.x; acc.y = r0 * v.y;
        }
        const float2* X2 = (const float2*)J.X;
        for (int seg = 0; seg < n; seg += 32) {
            int rr = (seg == 0) ? i0 : ((seg == 32) ? i1 : i2);
            int m = min(n - seg, 32);
            #pragma unroll 8
            for (int t = 0; t < m; t++) {
                int c = __shfl_sync(~0u, rr, t);
                float2 v = X2[c*32 + lane];
                acc.x += v.x; acc.y += v.y;
            }
        }
        if (RSOUT) { float sc = J.rs[row]; acc.x *= sc; acc.y *= sc; }
        ((float2*)J.out)[row*32 + lane] = acc;
    }
}

// ---------------- final: Z=Hm*S ; M=dv*Z+X ; X'=M@w+b ; Xs'=dv*X' ----------------
struct FHalf {
    const int* cols; int stride; const int* cnt;
    const float* S; float* Xbuf; float* Xs; const float* dv;
    float* outp; int n;
};

__device__ __forceinline__ void final_pair(const FHalf& A, const FHalf& B,
                                           const float* w, const float* b,
                                           int gw, int nwarp, int lane) {
    int ntot = A.n + B.n;
    for (int r = gw; r < ntot; r += nwarp) {
        const FHalf& J = (r < A.n) ? A : B;
        int row = (r < A.n) ? r : r - A.n;
        int n = min(J.cnt[row], J.stride);
        const int* cp = J.cols + row * J.stride;
        int i0 = 0, i1 = 0, i2 = 0;
        if (lane      < n) i0 = cp[lane];
        if (lane + 32 < n) i1 = cp[lane + 32];
        if (lane + 64 < n) i2 = cp[lane + 64];
        float2 acc = make_float2(0.f, 0.f);
        const float2* S2 = (const float2*)J.S;
        for (int seg = 0; seg < n; seg += 32) {
            int rr = (seg == 0) ? i0 : ((seg == 32) ? i1 : i2);
            int m = min(n - seg, 32);
            #pragma unroll 8
            for (int t = 0; t < m; t++) {
                int c = __shfl_sync(~0u, rr, t);
                float2 v = S2[c*32 + lane];
                acc.x += v.x; acc.y += v.y;
            }
        }
        float dvr = J.dv[row];
        float2 x0 = ((const float2*)J.Xbuf)[row*32 + lane];
        float2 m2 = make_float2(dvr*acc.x + x0.x, dvr*acc.y + x0.y);
        const float2* W2 = (const float2*)w;
        float2 o = __ldg((const float2*)b + lane);
        #pragma unroll
        for (int k = 0; k < 64; k++) {
            float mk = __shfl_sync(~0u, (k & 1) ? m2.y : m2.x, k >> 1);
            float2 wk = __ldg(&W2[k*32 + lane]);
            o.x += mk*wk.x; o.y += mk*wk.y;
        }
        ((float2*)J.Xbuf)[row*32 + lane] = o;
        ((float2*)J.Xs)[row*32 + lane]   = make_float2(dvr*o.x, dvr*o.y);
        ((float2*)(J.outp + (size_t)row * 192))[lane] = o;
    }
}

// ---------------- the single persistent kernel ----------------
__global__ void __launch_bounds__(NTHR, 4) k_all(
    const uint4* __restrict__ H,
    const float* __restrict__ ue, const float* __restrict__ ie,
    const float* __restrict__ w0, const float* __restrict__ b0,
    const float* __restrict__ w1, const float* __restrict__ b1,
    float* __restrict__ out)
{
    const int tid  = blockIdx.x * NTHR + threadIdx.x;
    const int nthr = gridDim.x * NTHR;
    const int gw   = tid >> 5, nwarp = nthr >> 5, lane = threadIdx.x & 31;

    // ---- stage 0: zero counters + copy embeddings + level-0 output ----
    for (int i = tid; i < NU; i += nthr) g_ucnt[i] = 0;
    for (int i = tid; i < NI; i += nthr) g_icnt[i] = 0;
    for (int i = tid; i < NU*DE; i += nthr) {
        float v = ue[i]; g_Xu[i] = v;
        out[(i >> 6)*192 + (i & 63)] = v;
    }
    for (int i = tid; i < NI*DE; i += nthr) {
        float v = ie[i]; g_Xi[i] = v;
        out[OU + (i >> 6)*192 + (i & 63)] = v;
    }
    gsync();

    // ---- stage 1: scan dense H, high-MLP (8 unconditional LDG.128 per thread/step) ----
    {
        const int total = NU * (NI/4);               // uint4 elements, mult of 256
        for (int base = gw * 256; base < total; base += nwarp * 256) {
            uint4 v[8];
            #pragma unroll
            for (int k = 0; k < 8; k++)
                v[k] = __ldcs(H + base + lane + k*32);
            #pragma unroll
            for (int k = 0; k < 8; k++) {
                if (v[k].x | v[k].y | v[k].z | v[k].w) {
                    int idx = base + lane + k*32;
                    int u  = idx >> 10;
                    int c0 = (idx & 1023) << 2;
                    unsigned f[4] = {v[k].x, v[k].y, v[k].z, v[k].w};
                    #pragma unroll
                    for (int e = 0; e < 4; e++) {
                        if (f[e]) {
                            int c = c0 + e;
                            int p = atomicAdd(&g_ucnt[u], 1); if (p < US) g_ucols[u*US + p] = c;
                            int q = atomicAdd(&g_icnt[c], 1); if (q < IS) g_icols[c*IS + q] = u;
                        }
                    }
                }
            }
        }
    }
    gsync();

    // ---- stage 2: g1 = H^T * rowsum(H) ; hci = H * colsum(H) ----
    for (int r = gw; r < NI + NU; r += nwarp) {
        float s = 0.f;
        if (r < NI) {
            int i = r, n = min(g_icnt[i], IS);
            const int* cp = g_icols + i*IS;
            for (int t = lane; t < n; t += 32) s += (float)g_ucnt[cp[t]];
            for (int o = 16; o; o >>= 1) s += __shfl_down_sync(~0u, s, o);
            if (!lane) g_g1[i] = s;
        } else {
            int u = r - NI, n = min(g_ucnt[u], US);
            const int* cp = g_ucols + u*US;
            for (int t = lane; t < n; t += 32) s += (float)g_icnt[cp[t]];
            for (int o = 16; o; o >>= 1) s += __shfl_down_sync(~0u, s, o);
            if (!lane) g_hci[u] = s;
        }
    }
    gsync();

    // ---- stage 3: norms (dv, de1^2, de2^2) + prescale Xs = dv ⊙ X ----
    for (int r = gw; r < NU + NI; r += nwarp) {
        float s = 0.f;
        if (r < NU) {
            int u = r, n = min(g_ucnt[u], US);
            const int* cp = g_ucols + u*US;
            for (int t = lane; t < n; t += 32) s += g_g1[cp[t]];
            for (int o = 16; o; o >>= 1) s += __shfl_xor_sync(~0u, s, o);
            float ru = (float)g_ucnt[u];
            float dv = rsqrtf(ru + s + EPSF);
            if (!lane) {
                g_dvu[u]  = dv;
                g_de1i[u] = 1.0f / (ru + EPSF);
                g_de2i[u] = 1.0f / (s + EPSF);
            }
            float2 x = ((const float2*)g_Xu)[u*32 + lane];
            ((float2*)g_Xsu)[u*32 + lane] = make_float2(dv*x.x, dv*x.y);
        } else {
            int i = r - NU, n = min(g_icnt[i], IS);
            const int* cp = g_icols + i*IS;
            for (int t = lane; t < n; t += 32) s += g_hci[cp[t]];
            for (int o = 16; o; o >>= 1) s += __shfl_xor_sync(~0u, s, o);
            float ci = (float)g_icnt[i];
            float dv = rsqrtf(ci + s + EPSF);
            if (!lane) {
                g_dvi[i]  = dv;
                g_de1u[i] = 1.0f / (ci + EPSF);
                g_de2u[i] = 1.0f / (s + EPSF);
            }
            float2 x = ((const float2*)g_Xi)[i*32 + lane];
            ((float2*)g_Xsi)[i*32 + lane] = make_float2(dv*x.x, dv*x.y);
        }
    }
    gsync();

    // ---- two layers ----
    const float* wv[2] = { w0, w1 };
    const float* bv[2] = { b0, b1 };
    for (int l = 0; l < 2; l++) {
        Half a, b2;
        // S1: Y1 = Hm^T (dv ⊙ X)   (prescaled input, no per-nnz scale)
        a  = { g_icols, IS, g_icnt, g_Xsu, g_Y1u, nullptr, nullptr, NI };
        b2 = { g_ucols, US, g_ucnt, g_Xsi, g_Y1i, nullptr, nullptr, NU };
        spmm_pair<false, false>(a, b2, gw, nwarp, lane);
        gsync();
        // S2: P = Hm Y1
        a  = { g_ucols, US, g_ucnt, g_Y1u, g_An, nullptr, nullptr, NU };
        b2 = { g_icols, IS, g_icnt, g_Y1i, g_Bn, nullptr, nullptr, NI };
        spmm_pair<false, false>(a, b2, gw, nwarp, lane);
        gsync();
        // S3: Y2 = de2^2 ⊙ (Hm^T P)   (scale folded into store)
        a  = { g_icols, IS, g_icnt, g_An, g_Am, g_de2u, nullptr, NI };
        b2 = { g_ucols, US, g_ucnt, g_Bn, g_Bm, g_de2i, nullptr, NU };
        spmm_pair<true, false>(a, b2, gw, nwarp, lane);
        gsync();
        // S4: Q = Hm Y2
        a  = { g_ucols, US, g_ucnt, g_Am, g_An, nullptr, nullptr, NU };
        b2 = { g_icols, IS, g_icnt, g_Bm, g_Bn, nullptr, nullptr, NI };
        spmm_pair<false, false>(a, b2, gw, nwarp, lane);
        gsync();
        // S5: S = de1^2 ⊙ Y1 + Hm^T Q
        a  = { g_icols, IS, g_icnt, g_An, g_Am, g_de1u, g_Y1u, NI };
        b2 = { g_ucols, US, g_ucnt, g_Bn, g_Bm, g_de1i, g_Y1i, NU };
        spmm_pair<false, true>(a, b2, gw, nwarp, lane);
        gsync();
        // S6: M = dv ⊙ (Hm S) + X ; X' = M@w + b ; Xs' = dv ⊙ X' ; write out slice
        FHalf fa = { g_ucols, US, g_ucnt, g_Am, g_Xu, g_Xsu, g_dvu, out + 64*(l+1),      NU };
        FHalf fb = { g_icols, IS, g_icnt, g_Bm, g_Xi, g_Xsi, g_dvi, out + OU + 64*(l+1), NI };
        final_pair(fa, fb, wv[l], bv[l], gw, nwarp, lane);
        if (l == 0) gsync();
    }
}

// ---------------- host launch: ONE kernel, graph-capturable ----------------
extern "C" void kernel_launch(void* const* d_in, const int* in_sizes, int n_in,
                              void* d_out, int out_size) {
    const uint4* H  = (const uint4*)d_in[0];
    const float* ue = (const float*)d_in[1];
    const float* ie = (const float*)d_in[2];
    const float* w0 = (const float*)d_in[3];
    const float* b0 = (const float*)d_in[4];
    const float* w1 = (const float*)d_in[5];
    const float* b1 = (const float*)d_in[6];
    float* out = (float*)d_out;

    k_all<<<NBLK, NTHR>>>(H, ue, ie, w0, b0, w1, b1, out);
}

// round 4
// speedup vs baseline: 1.4894x; 1.1642x over previous
#include <cuda_runtime.h>

#define NU 8192
#define NI 4096
#define DE 64
#define US 64          // ELL stride, user rows (deg ~Poisson(20.5))
#define IS 96          // ELL stride, item rows (deg ~Poisson(41))
#define EPSF 1e-7f
#define OU (NU*192)
#define NBLK 592       // 148 SMs * 4 CTAs — co-resident via __launch_bounds__(256,4)
#define NTHR 256

// ---------------- device scratch (no allocations) ----------------
__device__ int g_ucnt[NU];
__device__ int g_icnt[NI];
__device__ int g_ucols[NU*US];     // ELL rows of H   (user -> items), padded w/ dummy NI
__device__ int g_icols[NI*IS];     // ELL rows of H^T (item -> users), padded w/ dummy NU

__device__ float g_g1[NI], g_hci[NU];
__device__ float g_dvu[NU], g_de1u[NI], g_de2u[NI];
__device__ float g_dvi[NI], g_de1i[NU], g_de2i[NU];

__device__ float g_Xu[NU*DE],  g_Xi[NI*DE];
// gather-source buffers carry ONE extra all-zero row (dummy target for ELL padding)
__device__ float g_Xsu[(NU+1)*DE], g_Xsi[(NI+1)*DE];   // dv ⊙ X
__device__ float g_Y1u[(NI+1)*DE], g_Y1i[(NU+1)*DE];
__device__ float g_An[(NU+1)*DE],  g_Am[(NI+1)*DE];
__device__ float g_Bn[(NI+1)*DE],  g_Bm[(NU+1)*DE];

__device__ unsigned g_bar_count = 0;
__device__ volatile unsigned g_bar_gen = 0;

// software grid barrier; all NBLK blocks co-resident. __threadfence (gpu scope)
// flushes L1 on both sides, so plain cached loads of mutable globals are safe
// across stages.
__device__ __forceinline__ void gsync() {
    __syncthreads();
    if (threadIdx.x == 0) {
        __threadfence();
        unsigned gen = g_bar_gen;
        if (atomicAdd(&g_bar_count, 1u) == gridDim.x - 1) {
            g_bar_count = 0;
            __threadfence();
            g_bar_gen = gen + 1;
        } else {
            while (g_bar_gen == gen) __nanosleep(32);
        }
        __threadfence();
    }
    __syncthreads();
}

// ---- core gather: n8 is a multiple of 8; every group is 8 unconditional loads ----
__device__ __forceinline__ void gather8(float2& acc, const float2* __restrict__ X2,
                                        int i0, int i1, int i2, int n8, int lane) {
    for (int seg = 0; seg < n8; seg += 8) {
        int rr = (seg < 32) ? i0 : ((seg < 64) ? i1 : i2);
        int t0 = seg & 31;
        int c[8];
        #pragma unroll
        for (int k = 0; k < 8; k++) c[k] = __shfl_sync(~0u, rr, t0 + k);
        float2 v[8];
        #pragma unroll
        for (int k = 0; k < 8; k++) v[k] = X2[c[k]*32 + lane];
        #pragma unroll
        for (int k = 0; k < 8; k++) { acc.x += v[k].x; acc.y += v[k].y; }
    }
}

// ---------------- SpMM over two independent halves (warp per row) ----------------
struct Half {
    const int* cols; int stride; const int* cnt;
    const float* X; float* out;
    const float* rs;            // RSOUT -> store scale, INIT -> init coeff
    const float* init;
    int n;
};

template<bool RSOUT, bool INIT>
__device__ __forceinline__ void spmm_pair(const Half& A, const Half& B,
                                          int gw, int nwarp, int lane) {
    int ntot = A.n + B.n;
    for (int r = gw; r < ntot; r += nwarp) {
        const Half& J = (r < A.n) ? A : B;
        int row = (r < A.n) ? r : r - A.n;
        int st = J.stride;
        int n  = min(J.cnt[row], st);
        int n8 = (n + 7) & ~7;
        const int* cp = J.cols + row * st;
        int i0 = cp[lane];
        int i1 = cp[lane + 32];
        int i2 = (64 + lane < st) ? cp[lane + 64] : 0;
        float2 acc = make_float2(0.f, 0.f);
        if (INIT) {
            float r0 = J.rs[row];
            float2 v = ((const float2*)J.init)[row*32 + lane];
            acc.x = r0 * v.x; acc.y = r0 * v.y;
        }
        gather8(acc, (const float2*)J.X, i0, i1, i2, n8, lane);
        if (RSOUT) { float sc = J.rs[row]; acc.x *= sc; acc.y *= sc; }
        ((float2*)J.out)[row*32 + lane] = acc;
    }
}

// ---------------- final: Z=Hm*S ; M=dv*Z+X ; X'=M@w+b ; Xs'=dv*X' ----------------
struct FHalf {
    const int* cols; int stride; const int* cnt;
    const float* S; float* Xbuf; float* Xs; const float* dv;
    float* outp; int n;
};

__device__ __forceinline__ void final_pair(const FHalf& A, const FHalf& B,
                                           const float* w, const float* b,
                                           int gw, int nwarp, int lane) {
    int ntot = A.n + B.n;
    for (int r = gw; r < ntot; r += nwarp) {
        const FHalf& J = (r < A.n) ? A : B;
        int row = (r < A.n) ? r : r - A.n;
        int st = J.stride;
        int n  = min(J.cnt[row], st);
        int n8 = (n + 7) & ~7;
        const int* cp = J.cols + row * st;
        int i0 = cp[lane];
        int i1 = cp[lane + 32];
        int i2 = (64 + lane < st) ? cp[lane + 64] : 0;
        float2 acc = make_float2(0.f, 0.f);
        gather8(acc, (const float2*)J.S, i0, i1, i2, n8, lane);
        float dvr = J.dv[row];
        float2 x0 = ((const float2*)J.Xbuf)[row*32 + lane];
        float2 m2 = make_float2(dvr*acc.x + x0.x, dvr*acc.y + x0.y);
        const float2* W2 = (const float2*)w;
        float2 o = __ldg((const float2*)b + lane);
        #pragma unroll
        for (int k = 0; k < 64; k++) {
            float mk = __shfl_sync(~0u, (k & 1) ? m2.y : m2.x, k >> 1);
            float2 wk = __ldg(&W2[k*32 + lane]);
            o.x += mk*wk.x; o.y += mk*wk.y;
        }
        ((float2*)J.Xbuf)[row*32 + lane] = o;
        ((float2*)J.Xs)[row*32 + lane]   = make_float2(dvr*o.x, dvr*o.y);
        ((float2*)(J.outp + (size_t)row * 192))[lane] = o;
    }
}

// ---------------- the single persistent kernel ----------------
__global__ void __launch_bounds__(NTHR, 4) k_all(
    const uint4* __restrict__ H,
    const float* __restrict__ ue, const float* __restrict__ ie,
    const float* __restrict__ w0, const float* __restrict__ b0,
    const float* __restrict__ w1, const float* __restrict__ b1,
    float* __restrict__ out)
{
    const int tid  = blockIdx.x * NTHR + threadIdx.x;
    const int nthr = gridDim.x * NTHR;
    const int gw   = tid >> 5, nwarp = nthr >> 5, lane = threadIdx.x & 31;

    // ---- stage 0: zero counters + dummy rows, copy embeddings, level-0 output ----
    for (int i = tid; i < NU; i += nthr) g_ucnt[i] = 0;
    for (int i = tid; i < NI; i += nthr) g_icnt[i] = 0;
    if (tid < DE) {   // zero the dummy row of every gather-source buffer
        g_Xsu[NU*DE + tid] = 0.f; g_Y1i[NU*DE + tid] = 0.f;
        g_An [NU*DE + tid] = 0.f; g_Bm [NU*DE + tid] = 0.f;
        g_Xsi[NI*DE + tid] = 0.f; g_Y1u[NI*DE + tid] = 0.f;
        g_Am [NI*DE + tid] = 0.f; g_Bn [NI*DE + tid] = 0.f;
    }
    for (int i = tid; i < NU*DE; i += nthr) {
        float v = ue[i]; g_Xu[i] = v;
        out[(i >> 6)*192 + (i & 63)] = v;
    }
    for (int i = tid; i < NI*DE; i += nthr) {
        float v = ie[i]; g_Xi[i] = v;
        out[OU + (i >> 6)*192 + (i & 63)] = v;
    }
    gsync();

    // ---- stage 1: scan dense H, high-MLP (8 unconditional LDG.128 per thread/step) ----
    {
        const int total = NU * (NI/4);
        for (int base = gw * 256; base < total; base += nwarp * 256) {
            uint4 v[8];
            #pragma unroll
            for (int k = 0; k < 8; k++)
                v[k] = __ldcs(H + base + lane + k*32);
            #pragma unroll
            for (int k = 0; k < 8; k++) {
                if (v[k].x | v[k].y | v[k].z | v[k].w) {
                    int idx = base + lane + k*32;
                    int u  = idx >> 10;
                    int c0 = (idx & 1023) << 2;
                    unsigned f[4] = {v[k].x, v[k].y, v[k].z, v[k].w};
                    #pragma unroll
                    for (int e = 0; e < 4; e++) {
                        if (f[e]) {
                            int c = c0 + e;
                            int p = atomicAdd(&g_ucnt[u], 1); if (p < US) g_ucols[u*US + p] = c;
                            int q = atomicAdd(&g_icnt[c], 1); if (q < IS) g_icols[c*IS + q] = u;
                        }
                    }
                }
            }
        }
    }
    gsync();

    // ---- stage 2: g1/hci + fill ELL pad slots with dummy indices ----
    for (int r = gw; r < NI + NU; r += nwarp) {
        float s = 0.f;
        if (r < NI) {
            int i = r, n = min(g_icnt[i], IS);
            int n8 = (n + 7) & ~7;
            int* cpw = g_icols + i*IS;
            if (n + lane < n8) cpw[n + lane] = NU;      // dummy -> zero row
            for (int t = lane; t < n; t += 32) s += (float)g_ucnt[cpw[t]];
            for (int o = 16; o; o >>= 1) s += __shfl_down_sync(~0u, s, o);
            if (!lane) g_g1[i] = s;
        } else {
            int u = r - NI, n = min(g_ucnt[u], US);
            int n8 = (n + 7) & ~7;
            int* cpw = g_ucols + u*US;
            if (n + lane < n8) cpw[n + lane] = NI;      // dummy -> zero row
            for (int t = lane; t < n; t += 32) s += (float)g_icnt[cpw[t]];
            for (int o = 16; o; o >>= 1) s += __shfl_down_sync(~0u, s, o);
            if (!lane) g_hci[u] = s;
        }
    }
    gsync();

    // ---- stage 3: norms (dv, de1^2, de2^2) + prescale Xs = dv ⊙ X ----
    for (int r = gw; r < NU + NI; r += nwarp) {
        float s = 0.f;
        if (r < NU) {
            int u = r, n = min(g_ucnt[u], US);
            const int* cp = g_ucols + u*US;
            for (int t = lane; t < n; t += 32) s += g_g1[cp[t]];
            for (int o = 16; o; o >>= 1) s += __shfl_xor_sync(~0u, s, o);
            float ru = (float)g_ucnt[u];
            float dv = rsqrtf(ru + s + EPSF);
            if (!lane) {
                g_dvu[u]  = dv;
                g_de1i[u] = 1.0f / (ru + EPSF);
                g_de2i[u] = 1.0f / (s + EPSF);
            }
            float2 x = ((const float2*)g_Xu)[u*32 + lane];
            ((float2*)g_Xsu)[u*32 + lane] = make_float2(dv*x.x, dv*x.y);
        } else {
            int i = r - NU, n = min(g_icnt[i], IS);
            const int* cp = g_icols + i*IS;
            for (int t = lane; t < n; t += 32) s += g_hci[cp[t]];
            for (int o = 16; o; o >>= 1) s += __shfl_xor_sync(~0u, s, o);
            float ci = (float)g_icnt[i];
            float dv = rsqrtf(ci + s + EPSF);
            if (!lane) {
                g_dvi[i]  = dv;
                g_de1u[i] = 1.0f / (ci + EPSF);
                g_de2u[i] = 1.0f / (s + EPSF);
            }
            float2 x = ((const float2*)g_Xi)[i*32 + lane];
            ((float2*)g_Xsi)[i*32 + lane] = make_float2(dv*x.x, dv*x.y);
        }
    }
    gsync();

    // ---- two layers ----
    const float* wv[2] = { w0, w1 };
    const float* bv[2] = { b0, b1 };
    for (int l = 0; l < 2; l++) {
        Half a, b2;
        // S1: Y1 = Hm^T (dv ⊙ X)
        a  = { g_icols, IS, g_icnt, g_Xsu, g_Y1u, nullptr, nullptr, NI };
        b2 = { g_ucols, US, g_ucnt, g_Xsi, g_Y1i, nullptr, nullptr, NU };
        spmm_pair<false, false>(a, b2, gw, nwarp, lane);
        gsync();
        // S2: P = Hm Y1
        a  = { g_ucols, US, g_ucnt, g_Y1u, g_An, nullptr, nullptr, NU };
        b2 = { g_icols, IS, g_icnt, g_Y1i, g_Bn, nullptr, nullptr, NI };
        spmm_pair<false, false>(a, b2, gw, nwarp, lane);
        gsync();
        // S3: Y2 = de2^2 ⊙ (Hm^T P)
        a  = { g_icols, IS, g_icnt, g_An, g_Am, g_de2u, nullptr, NI };
        b2 = { g_ucols, US, g_ucnt, g_Bn, g_Bm, g_de2i, nullptr, NU };
        spmm_pair<true, false>(a, b2, gw, nwarp, lane);
        gsync();
        // S4: Q = Hm Y2
        a  = { g_ucols, US, g_ucnt, g_Am, g_An, nullptr, nullptr, NU };
        b2 = { g_icols, IS, g_icnt, g_Bm, g_Bn, nullptr, nullptr, NI };
        spmm_pair<false, false>(a, b2, gw, nwarp, lane);
        gsync();
        // S5: S = de1^2 ⊙ Y1 + Hm^T Q
        a  = { g_icols, IS, g_icnt, g_An, g_Am, g_de1u, g_Y1u, NI };
        b2 = { g_ucols, US, g_ucnt, g_Bn, g_Bm, g_de1i, g_Y1i, NU };
        spmm_pair<false, true>(a, b2, gw, nwarp, lane);
        gsync();
        // S6: M = dv ⊙ (Hm S) + X ; X' = M@w + b ; Xs' = dv ⊙ X' ; write out slice
        FHalf fa = { g_ucols, US, g_ucnt, g_Am, g_Xu, g_Xsu, g_dvu, out + 64*(l+1),      NU };
        FHalf fb = { g_icols, IS, g_icnt, g_Bm, g_Xi, g_Xsi, g_dvi, out + OU + 64*(l+1), NI };
        final_pair(fa, fb, wv[l], bv[l], gw, nwarp, lane);
        if (l == 0) gsync();
    }
}

// ---------------- host launch: ONE kernel, graph-capturable ----------------
extern "C" void kernel_launch(void* const* d_in, const int* in_sizes, int n_in,
                              void* d_out, int out_size) {
    const uint4* H  = (const uint4*)d_in[0];
    const float* ue = (const float*)d_in[1];
    const float* ie = (const float*)d_in[2];
    const float* w0 = (const float*)d_in[3];
    const float* b0 = (const float*)d_in[4];
    const float* w1 = (const float*)d_in[5];
    const float* b1 = (const float*)d_in[6];
    float* out = (float*)d_out;

    k_all<<<NBLK, NTHR>>>(H, ue, ie, w0, b0, w1, b1, out);
}